// round 4
// baseline (speedup 1.0000x reference)
#include <cuda_runtime.h>
#include <cstdint>

// ---------------------------------------------------------------------------
// LoRARowParallelLinear, mma.sync tf32 (compute_103-safe).
//   conv:   RNA-round + repack x, W, lora_A into FRAGMENT-MAJOR layouts
//           (smem-staged for coalescing); build Bcat[n][s*16+r].
//   pass A: u[T,128] = mask*scal*(x @ lora_A^T), written in A-frag layout.
//   pass B: y = x @ W^T (K=4096) + u @ Bcat^T (K-ext 128, same accum) + bias.
// Main GEMM: CTA 128x256, 8 warps, warp tile 64x64 (acc 128 regs), BK=32, 3-stage.
// ---------------------------------------------------------------------------

#define DEVINL static __device__ __forceinline__

namespace {
constexpr int TOK = 8192, DIN = 4096, DOUT = 4096;
constexpr int KB_MAIN = DIN / 8;   // 512
constexpr int KB_EXT  = 16;        // 128/8
}

// scratch (allocation-free: __device__ globals), all fragment-major
__device__ float g_xc  [TOK  * DIN];   // A-blocks: [TOK/16][512][128]
__device__ float g_wc  [DOUT * DIN];   // B-blocks: [DOUT/8][512][64]
__device__ float g_lac [128  * DIN];   // B-blocks: [16][512][64]
__device__ float g_bcat[DOUT * 128];   // B-blocks: [DOUT/8][16][64]
__device__ float g_u   [TOK  * 128];   // A-blocks: [TOK/16][16][128]

DEVINL uint32_t f2tf(float f) { uint32_t u; asm("cvt.rna.tf32.f32 %0, %1;" : "=r"(u) : "f"(f)); return u; }
DEVINL float    rna(float f)  { return __uint_as_float(f2tf(f)); }

DEVINL void mma_tf32(float& d0, float& d1, float& d2, float& d3,
                     uint32_t a0, uint32_t a1, uint32_t a2, uint32_t a3,
                     uint32_t b0, uint32_t b1)
{
    asm volatile(
        "mma.sync.aligned.m16n8k8.row.col.f32.tf32.tf32.f32 "
        "{%0,%1,%2,%3},{%4,%5,%6,%7},{%8,%9},{%0,%1,%2,%3};"
        : "+f"(d0), "+f"(d1), "+f"(d2), "+f"(d3)
        : "r"(a0), "r"(a1), "r"(a2), "r"(a3), "r"(b0), "r"(b1));
}

DEVINL void cpa16(float* smem_dst, const float* gsrc) {
    uint32_t s = (uint32_t)__cvta_generic_to_shared(smem_dst);
    asm volatile("cp.async.cg.shared.global [%0], [%1], 16;" :: "r"(s), "l"(gsrc));
}
DEVINL void cpcommit() { asm volatile("cp.async.commit_group;"); }
template <int N> DEVINL void cpwait() { asm volatile("cp.async.wait_group %0;" :: "n"(N)); }

// ---------------------------------------------------------------------------
// Conversion: RNA-round + repack, staged through smem for coalescing.
// ---------------------------------------------------------------------------
__global__ void __launch_bounds__(256) conv_kernel(
    const float* __restrict__ x, const float* __restrict__ w,
    const float* __restrict__ la, const float* __restrict__ lb)
{
    __shared__ float st[8][16 * 36];
    const int tid  = threadIdx.x;
    const int lane = tid & 31, warp = tid >> 5;
    const int gwarp = blockIdx.x * 8 + warp;
    const int nwarp = gridDim.x * 8;
    float* s = st[warp];
    const int r0 = lane >> 2, c0 = lane & 3;
    const int rr = lane >> 3, cc = (lane & 7) * 4;

    // x -> g_xc (A-frag). Superblock = 16 rows x 32 cols (4 k-blocks).
    for (int sb = gwarp; sb < 512 * 128; sb += nwarp) {
        const int mt = sb >> 7, kt4 = sb & 127;
        const float* base = x + (size_t)(mt * 16) * DIN + kt4 * 32;
        #pragma unroll
        for (int p = 0; p < 4; p++) {
            const int r = p * 4 + rr;
            float4 v = *reinterpret_cast<const float4*>(base + (size_t)r * DIN + cc);
            v.x = rna(v.x); v.y = rna(v.y); v.z = rna(v.z); v.w = rna(v.w);
            *reinterpret_cast<float4*>(s + r * 36 + cc) = v;
        }
        __syncwarp();
        #pragma unroll
        for (int kb = 0; kb < 4; kb++) {
            float4 v;
            v.x = s[r0 * 36 + kb * 8 + c0];
            v.y = s[(r0 + 8) * 36 + kb * 8 + c0];
            v.z = s[r0 * 36 + kb * 8 + c0 + 4];
            v.w = s[(r0 + 8) * 36 + kb * 8 + c0 + 4];
            *reinterpret_cast<float4*>(g_xc + ((size_t)mt * 512 + kt4 * 4 + kb) * 128 + lane * 4) = v;
        }
        __syncwarp();
    }

    // w -> g_wc (B-frag). Superblock = 8 rows x 32 cols.
    for (int sb = gwarp; sb < 512 * 128; sb += nwarp) {
        const int nt = sb >> 7, kt4 = sb & 127;
        const float* base = w + (size_t)(nt * 8) * DIN + kt4 * 32;
        #pragma unroll
        for (int p = 0; p < 2; p++) {
            const int r = p * 4 + rr;
            float4 v = *reinterpret_cast<const float4*>(base + (size_t)r * DIN + cc);
            v.x = rna(v.x); v.y = rna(v.y); v.z = rna(v.z); v.w = rna(v.w);
            *reinterpret_cast<float4*>(s + r * 36 + cc) = v;
        }
        __syncwarp();
        #pragma unroll
        for (int kb = 0; kb < 4; kb++) {
            float2 v;
            v.x = s[r0 * 36 + kb * 8 + c0];
            v.y = s[r0 * 36 + kb * 8 + c0 + 4];
            *reinterpret_cast<float2*>(g_wc + ((size_t)nt * 512 + kt4 * 4 + kb) * 64 + lane * 2) = v;
        }
        __syncwarp();
    }

    // lora_A -> g_lac (B-frag, 16 n-tiles)
    for (int sb = gwarp; sb < 16 * 128; sb += nwarp) {
        const int nt = sb >> 7, kt4 = sb & 127;
        const float* base = la + (size_t)(nt * 8) * DIN + kt4 * 32;
        #pragma unroll
        for (int p = 0; p < 2; p++) {
            const int r = p * 4 + rr;
            float4 v = *reinterpret_cast<const float4*>(base + (size_t)r * DIN + cc);
            v.x = rna(v.x); v.y = rna(v.y); v.z = rna(v.z); v.w = rna(v.w);
            *reinterpret_cast<float4*>(s + r * 36 + cc) = v;
        }
        __syncwarp();
        #pragma unroll
        for (int kb = 0; kb < 4; kb++) {
            float2 v;
            v.x = s[r0 * 36 + kb * 8 + c0];
            v.y = s[r0 * 36 + kb * 8 + c0 + 4];
            *reinterpret_cast<float2*>(g_lac + ((size_t)nt * 512 + kt4 * 4 + kb) * 64 + lane * 2) = v;
        }
        __syncwarp();
    }

    // lora_B [8][DOUT][16] -> g_bcat (B-frag [DOUT/8][16][64]): Bcat[n][s*16+r]=lB[s][n][r]
    const int nth = gridDim.x * blockDim.x;
    const int gt  = blockIdx.x * 256 + tid;
    for (int i = gt; i < 8 * DOUT * 16; i += nth) {
        const int sl = i >> 16;
        const int n  = (i >> 4) & 4095;
        const int r  = i & 15;
        const float val = rna(lb[i]);
        const int kc  = sl * 16 + r;
        const int nt  = n >> 3, kb = kc >> 3, col = kc & 7;
        const int off = ((n & 7) * 4 + (col & 3)) * 2 + (col >> 2);
        g_bcat[((size_t)nt * 16 + kb) * 64 + off] = val;
    }
}

// ---------------------------------------------------------------------------
// Pass A: u = mask*scal*(x @ lora_A^T) -> g_u (A-frag layout).
// CTA 128x128, 8 warps (32x64 warp tile), BK=32, 3 stages. (unchanged from R3)
// ---------------------------------------------------------------------------
__global__ void __launch_bounds__(256, 1) gemm_lora(
    const int* __restrict__ t2s, const float* __restrict__ scal)
{
    constexpr int A_ST = 128 * 32, B_ST = 128 * 32, STW = A_ST + B_ST;
    extern __shared__ float sm[];
    const int tid = threadIdx.x, lane = tid & 31, warp = tid >> 5;
    const int wn = warp & 1, wm = warp >> 1;
    const int bm = blockIdx.y;

    float acc[2][8][4];
    #pragma unroll
    for (int i = 0; i < 2; i++)
        #pragma unroll
        for (int j = 0; j < 8; j++)
            #pragma unroll
            for (int k = 0; k < 4; k++) acc[i][j][k] = 0.f;

    auto load_stage = [&](int f, int buf) {
        float* sA = sm + buf * STW;
        float* sB = sA + A_ST;
        #pragma unroll
        for (int q = tid; q < 128 * 8; q += 256) {
            const int mt = q >> 7, rem = q & 127, kt = rem >> 5, c = rem & 31;
            cpa16(sA + (mt * 4 + kt) * 128 + c * 4,
                  g_xc + ((size_t)(bm * 8 + mt) * KB_MAIN + f * 4 + kt) * 128 + c * 4);
        }
        #pragma unroll
        for (int q = tid; q < 128 * 8; q += 256) {
            const int nt = q >> 6, kt = (q >> 4) & 3, c = q & 15;
            cpa16(sB + (nt * 4 + kt) * 64 + c * 4,
                  g_lac + ((size_t)nt * KB_MAIN + f * 4 + kt) * 64 + c * 4);
        }
    };

    load_stage(0, 0); cpcommit();
    load_stage(1, 1); cpcommit();

    for (int ci = 0; ci < 128; ci++) {
        cpwait<1>();
        __syncthreads();
        if (ci + 2 < 128) load_stage(ci + 2, (ci + 2) % 3);
        cpcommit();

        const uint32_t* sA = reinterpret_cast<const uint32_t*>(sm + (ci % 3) * STW);
        const uint32_t* sB = sA + A_ST;
        const uint32_t* aw = sA + (wm * 2) * 4 * 128 + lane * 4;
        const uint32_t* bw = sB + (wn * 8) * 4 * 64 + lane * 2;

        #pragma unroll
        for (int kt = 0; kt < 4; kt++) {
            uint4 a[2];
            a[0] = *reinterpret_cast<const uint4*>(aw + kt * 128);
            a[1] = *reinterpret_cast<const uint4*>(aw + (4 + kt) * 128);
            uint2 b[8];
            #pragma unroll
            for (int j = 0; j < 8; j++)
                b[j] = *reinterpret_cast<const uint2*>(bw + (j * 4 + kt) * 64);
            #pragma unroll
            for (int i = 0; i < 2; i++)
                #pragma unroll
                for (int j = 0; j < 8; j++)
                    mma_tf32(acc[i][j][0], acc[i][j][1], acc[i][j][2], acc[i][j][3],
                             a[i].x, a[i].y, a[i].z, a[i].w, b[j].x, b[j].y);
        }
    }

    // epilogue: mask * scale, write g_u in A-frag layout
    #pragma unroll
    for (int i = 0; i < 2; i++) {
        #pragma unroll
        for (int h = 0; h < 2; h++) {
            const int m    = bm * 128 + wm * 32 + i * 16 + h * 8 + (lane >> 2);
            const int slot = t2s[m];
            const float sc = (slot >= 0) ? scal[slot] : 0.f;
            const int mt = m >> 4, row = m & 15;
            const int rowoff = (row & 7) * 4, regbit = row >> 3;
            float* ublk = g_u + (size_t)mt * 16 * 128;
            #pragma unroll
            for (int j = 0; j < 8; j++) {
                #pragma unroll
                for (int r = 0; r < 2; r++) {
                    const int nn  = wn * 64 + j * 8 + (lane & 3) * 2 + r;
                    const int kb  = nn >> 3, col = nn & 7;
                    const int off = (rowoff + (col & 3)) * 4 + regbit + 2 * (col >> 2);
                    const float val = ((nn >> 4) == slot)
                                      ? rna(acc[i][j][h * 2 + r] * sc) : 0.f;
                    ublk[kb * 128 + off] = val;
                }
            }
        }
    }
}

// ---------------------------------------------------------------------------
// Pass B: y = x @ W^T (+ LoRA K-ext) + bias.
// CTA 128x256, 8 warps, warp tile 64x64, BK=32, 3 stages, 144KB smem.
// ---------------------------------------------------------------------------
__global__ void __launch_bounds__(256, 1) gemm_main(
    float* __restrict__ C, const float* __restrict__ bias)
{
    constexpr int A_ST = 128 * 32, B_ST = 256 * 32, STW = A_ST + B_ST;
    extern __shared__ float sm[];
    const int tid = threadIdx.x, lane = tid & 31, warp = tid >> 5;
    const int wm = warp >> 2, wn = warp & 3;
    const int bm = blockIdx.y, bn = blockIdx.x;

    float acc[4][8][4];
    #pragma unroll
    for (int i = 0; i < 4; i++)
        #pragma unroll
        for (int j = 0; j < 8; j++)
            #pragma unroll
            for (int k = 0; k < 4; k++) acc[i][j][k] = 0.f;

    auto load_stage = [&](int f, int buf) {
        float* sA = sm + buf * STW;
        float* sB = sA + A_ST;
        #pragma unroll
        for (int q = tid; q < 128 * 8; q += 256) {
            const int mt = q >> 7, rem = q & 127, kt = rem >> 5, c = rem & 31;
            const float* src = (f < 128)
                ? g_xc + ((size_t)(bm * 8 + mt) * KB_MAIN + f * 4 + kt) * 128 + c * 4
                : g_u  + ((size_t)(bm * 8 + mt) * KB_EXT + (f - 128) * 4 + kt) * 128 + c * 4;
            cpa16(sA + (mt * 4 + kt) * 128 + c * 4, src);
        }
        #pragma unroll
        for (int q = tid; q < 256 * 8; q += 256) {
            const int nt = q >> 6, kt = (q >> 4) & 3, c = q & 15;
            const float* src = (f < 128)
                ? g_wc   + ((size_t)(bn * 32 + nt) * KB_MAIN + f * 4 + kt) * 64 + c * 4
                : g_bcat + ((size_t)(bn * 32 + nt) * KB_EXT + (f - 128) * 4 + kt) * 64 + c * 4;
            cpa16(sB + (nt * 4 + kt) * 64 + c * 4, src);
        }
    };

    load_stage(0, 0); cpcommit();
    load_stage(1, 1); cpcommit();

    for (int ci = 0; ci < 132; ci++) {
        cpwait<1>();
        __syncthreads();
        if (ci + 2 < 132) load_stage(ci + 2, (ci + 2) % 3);
        cpcommit();

        const uint32_t* sA = reinterpret_cast<const uint32_t*>(sm + (ci % 3) * STW);
        const uint32_t* sB = sA + A_ST;
        const uint32_t* aw = sA + (wm * 4) * 4 * 128 + lane * 4;
        const uint32_t* bw = sB + (wn * 8) * 4 * 64 + lane * 2;

        #pragma unroll
        for (int kt = 0; kt < 4; kt++) {
            uint4 a[4];
            #pragma unroll
            for (int i = 0; i < 4; i++)
                a[i] = *reinterpret_cast<const uint4*>(aw + (i * 4 + kt) * 128);
            uint2 b[8];
            #pragma unroll
            for (int j = 0; j < 8; j++)
                b[j] = *reinterpret_cast<const uint2*>(bw + (j * 4 + kt) * 64);
            #pragma unroll
            for (int i = 0; i < 4; i++)
                #pragma unroll
                for (int j = 0; j < 8; j++)
                    mma_tf32(acc[i][j][0], acc[i][j][1], acc[i][j][2], acc[i][j][3],
                             a[i].x, a[i].y, a[i].z, a[i].w, b[j].x, b[j].y);
        }
    }

    // epilogue: + bias -> y
    const int nb = bn * 256 + wn * 64;
    #pragma unroll
    for (int i = 0; i < 4; i++) {
        #pragma unroll
        for (int h = 0; h < 2; h++) {
            const int m = bm * 128 + wm * 64 + i * 16 + h * 8 + (lane >> 2);
            float* crow = C + (size_t)m * DOUT + nb + (lane & 3) * 2;
            #pragma unroll
            for (int j = 0; j < 8; j++) {
                const float2 bv = *reinterpret_cast<const float2*>(
                    bias + nb + j * 8 + (lane & 3) * 2);
                float2 v;
                v.x = acc[i][j][h * 2 + 0] + bv.x;
                v.y = acc[i][j][h * 2 + 1] + bv.y;
                *reinterpret_cast<float2*>(crow + j * 8) = v;
            }
        }
    }
}

// ---------------------------------------------------------------------------
extern "C" void kernel_launch(void* const* d_in, const int* in_sizes, int n_in,
                              void* d_out, int out_size)
{
    const float* x    = (const float*)d_in[0];
    const int*   t2s  = (const int*)  d_in[1];
    const float* w    = (const float*)d_in[2];
    const float* bias = (const float*)d_in[3];
    const float* lA   = (const float*)d_in[4];
    const float* lB   = (const float*)d_in[5];
    const float* scal = (const float*)d_in[6];
    float*       y    = (float*)d_out;

    constexpr int SMEM0 = 3 * (128 + 128) * 32 * 4;  //  96 KB
    constexpr int SMEM1 = 3 * (128 + 256) * 32 * 4;  // 144 KB

    cudaFuncSetAttribute(gemm_lora, cudaFuncAttributeMaxDynamicSharedMemorySize, SMEM0);
    cudaFuncSetAttribute(gemm_main, cudaFuncAttributeMaxDynamicSharedMemorySize, SMEM1);

    conv_kernel<<<1184, 256>>>(x, w, lA, lB);
    gemm_lora<<<dim3(1, TOK / 128), 256, SMEM0>>>(t2s, scal);
    gemm_main<<<dim3(DOUT / 256, TOK / 128), 256, SMEM1>>>(y, bias);
}

// round 5
// speedup vs baseline: 1.0596x; 1.0596x over previous
#include <cuda_runtime.h>
#include <cstdint>

// ---------------------------------------------------------------------------
// LoRARowParallelLinear, mma.sync tf32 (compute_103-safe).
//   conv:   RNA-round + repack x, W, lora_A into FRAGMENT-MAJOR layouts;
//           build Bcat[n][s*16+r].
//   pass A: u[T,128] = mask*scal*(x @ lora_A^T), A-frag layout. CTA 64x128,
//           128 thr, 3 CTAs/SM.
//   pass B: y = x @ W^T (K=4096) + u @ Bcat^T (K-ext) + bias. CTA 128x128,
//           128 thr (4 warps, 64x64 warp tile), 96KB smem, 2 CTAs/SM so one
//           CTA's MMAs cover the other's barrier/load exposure.
// ---------------------------------------------------------------------------

#define DEVINL static __device__ __forceinline__

namespace {
constexpr int TOK = 8192, DIN = 4096, DOUT = 4096;
constexpr int KB_MAIN = DIN / 8;   // 512
constexpr int KB_EXT  = 16;        // 128/8
}

// scratch (allocation-free: __device__ globals), all fragment-major
__device__ float g_xc  [TOK  * DIN];   // A-blocks: [TOK/16][512][128]
__device__ float g_wc  [DOUT * DIN];   // B-blocks: [DOUT/8][512][64]
__device__ float g_lac [128  * DIN];   // B-blocks: [16][512][64]
__device__ float g_bcat[DOUT * 128];   // B-blocks: [DOUT/8][16][64]
__device__ float g_u   [TOK  * 128];   // A-blocks: [TOK/16][16][128]

DEVINL uint32_t f2tf(float f) { uint32_t u; asm("cvt.rna.tf32.f32 %0, %1;" : "=r"(u) : "f"(f)); return u; }
DEVINL float    rna(float f)  { return __uint_as_float(f2tf(f)); }

DEVINL void mma_tf32(float& d0, float& d1, float& d2, float& d3,
                     uint32_t a0, uint32_t a1, uint32_t a2, uint32_t a3,
                     uint32_t b0, uint32_t b1)
{
    asm volatile(
        "mma.sync.aligned.m16n8k8.row.col.f32.tf32.tf32.f32 "
        "{%0,%1,%2,%3},{%4,%5,%6,%7},{%8,%9},{%0,%1,%2,%3};"
        : "+f"(d0), "+f"(d1), "+f"(d2), "+f"(d3)
        : "r"(a0), "r"(a1), "r"(a2), "r"(a3), "r"(b0), "r"(b1));
}

DEVINL void cpa16(float* smem_dst, const float* gsrc) {
    uint32_t s = (uint32_t)__cvta_generic_to_shared(smem_dst);
    asm volatile("cp.async.cg.shared.global [%0], [%1], 16;" :: "r"(s), "l"(gsrc));
}
DEVINL void cpcommit() { asm volatile("cp.async.commit_group;"); }
template <int N> DEVINL void cpwait() { asm volatile("cp.async.wait_group %0;" :: "n"(N)); }

// ---------------------------------------------------------------------------
// Conversion: RNA-round + repack, staged through smem (unchanged from R4).
// ---------------------------------------------------------------------------
__global__ void __launch_bounds__(256) conv_kernel(
    const float* __restrict__ x, const float* __restrict__ w,
    const float* __restrict__ la, const float* __restrict__ lb)
{
    __shared__ float st[8][16 * 36];
    const int tid  = threadIdx.x;
    const int lane = tid & 31, warp = tid >> 5;
    const int gwarp = blockIdx.x * 8 + warp;
    const int nwarp = gridDim.x * 8;
    float* s = st[warp];
    const int r0 = lane >> 2, c0 = lane & 3;
    const int rr = lane >> 3, cc = (lane & 7) * 4;

    for (int sb = gwarp; sb < 512 * 128; sb += nwarp) {
        const int mt = sb >> 7, kt4 = sb & 127;
        const float* base = x + (size_t)(mt * 16) * DIN + kt4 * 32;
        #pragma unroll
        for (int p = 0; p < 4; p++) {
            const int r = p * 4 + rr;
            float4 v = *reinterpret_cast<const float4*>(base + (size_t)r * DIN + cc);
            v.x = rna(v.x); v.y = rna(v.y); v.z = rna(v.z); v.w = rna(v.w);
            *reinterpret_cast<float4*>(s + r * 36 + cc) = v;
        }
        __syncwarp();
        #pragma unroll
        for (int kb = 0; kb < 4; kb++) {
            float4 v;
            v.x = s[r0 * 36 + kb * 8 + c0];
            v.y = s[(r0 + 8) * 36 + kb * 8 + c0];
            v.z = s[r0 * 36 + kb * 8 + c0 + 4];
            v.w = s[(r0 + 8) * 36 + kb * 8 + c0 + 4];
            *reinterpret_cast<float4*>(g_xc + ((size_t)mt * 512 + kt4 * 4 + kb) * 128 + lane * 4) = v;
        }
        __syncwarp();
    }

    for (int sb = gwarp; sb < 512 * 128; sb += nwarp) {
        const int nt = sb >> 7, kt4 = sb & 127;
        const float* base = w + (size_t)(nt * 8) * DIN + kt4 * 32;
        #pragma unroll
        for (int p = 0; p < 2; p++) {
            const int r = p * 4 + rr;
            float4 v = *reinterpret_cast<const float4*>(base + (size_t)r * DIN + cc);
            v.x = rna(v.x); v.y = rna(v.y); v.z = rna(v.z); v.w = rna(v.w);
            *reinterpret_cast<float4*>(s + r * 36 + cc) = v;
        }
        __syncwarp();
        #pragma unroll
        for (int kb = 0; kb < 4; kb++) {
            float2 v;
            v.x = s[r0 * 36 + kb * 8 + c0];
            v.y = s[r0 * 36 + kb * 8 + c0 + 4];
            *reinterpret_cast<float2*>(g_wc + ((size_t)nt * 512 + kt4 * 4 + kb) * 64 + lane * 2) = v;
        }
        __syncwarp();
    }

    for (int sb = gwarp; sb < 16 * 128; sb += nwarp) {
        const int nt = sb >> 7, kt4 = sb & 127;
        const float* base = la + (size_t)(nt * 8) * DIN + kt4 * 32;
        #pragma unroll
        for (int p = 0; p < 2; p++) {
            const int r = p * 4 + rr;
            float4 v = *reinterpret_cast<const float4*>(base + (size_t)r * DIN + cc);
            v.x = rna(v.x); v.y = rna(v.y); v.z = rna(v.z); v.w = rna(v.w);
            *reinterpret_cast<float4*>(s + r * 36 + cc) = v;
        }
        __syncwarp();
        #pragma unroll
        for (int kb = 0; kb < 4; kb++) {
            float2 v;
            v.x = s[r0 * 36 + kb * 8 + c0];
            v.y = s[r0 * 36 + kb * 8 + c0 + 4];
            *reinterpret_cast<float2*>(g_lac + ((size_t)nt * 512 + kt4 * 4 + kb) * 64 + lane * 2) = v;
        }
        __syncwarp();
    }

    const int nth = gridDim.x * blockDim.x;
    const int gt  = blockIdx.x * 256 + tid;
    for (int i = gt; i < 8 * DOUT * 16; i += nth) {
        const int sl = i >> 16;
        const int n  = (i >> 4) & 4095;
        const int r  = i & 15;
        const float val = rna(lb[i]);
        const int kc  = sl * 16 + r;
        const int nt  = n >> 3, kb = kc >> 3, col = kc & 7;
        const int off = ((n & 7) * 4 + (col & 3)) * 2 + (col >> 2);
        g_bcat[((size_t)nt * 16 + kb) * 64 + off] = val;
    }
}

// ---------------------------------------------------------------------------
// Pass A: u = mask*scal*(x @ lora_A^T) -> g_u (A-frag layout).
// CTA 64x128, 128 threads (4 warps, warp 32x64), BK=32, 3 stages, 72KB, occ 3.
// ---------------------------------------------------------------------------
__global__ void __launch_bounds__(128, 3) gemm_lora(
    const int* __restrict__ t2s, const float* __restrict__ scal)
{
    constexpr int A_ST = 64 * 32, B_ST = 128 * 32, STW = A_ST + B_ST;
    extern __shared__ float sm[];
    const int tid = threadIdx.x, lane = tid & 31, warp = tid >> 5;
    const int wm = warp >> 1, wn = warp & 1;   // warp tile 32x64
    const int bm = blockIdx.y;

    float acc[2][8][4];
    #pragma unroll
    for (int i = 0; i < 2; i++)
        #pragma unroll
        for (int j = 0; j < 8; j++)
            #pragma unroll
            for (int k = 0; k < 4; k++) acc[i][j][k] = 0.f;

    auto load_stage = [&](int f, int buf) {
        float* sA = sm + buf * STW;
        float* sB = sA + A_ST;
        #pragma unroll
        for (int q = tid; q < 64 * 8; q += 128) {
            const int mt = q >> 7, rem = q & 127, kt = rem >> 5, c = rem & 31;
            cpa16(sA + (mt * 4 + kt) * 128 + c * 4,
                  g_xc + ((size_t)(bm * 4 + mt) * KB_MAIN + f * 4 + kt) * 128 + c * 4);
        }
        #pragma unroll
        for (int q = tid; q < 128 * 8; q += 128) {
            const int nt = q >> 6, kt = (q >> 4) & 3, c = q & 15;
            cpa16(sB + (nt * 4 + kt) * 64 + c * 4,
                  g_lac + ((size_t)nt * KB_MAIN + f * 4 + kt) * 64 + c * 4);
        }
    };

    load_stage(0, 0); cpcommit();
    load_stage(1, 1); cpcommit();

    for (int ci = 0; ci < 128; ci++) {
        cpwait<1>();
        __syncthreads();
        if (ci + 2 < 128) load_stage(ci + 2, (ci + 2) % 3);
        cpcommit();

        const uint32_t* sA = reinterpret_cast<const uint32_t*>(sm + (ci % 3) * STW);
        const uint32_t* sB = sA + A_ST;
        const uint32_t* aw = sA + (wm * 2) * 4 * 128 + lane * 4;
        const uint32_t* bw = sB + (wn * 8) * 4 * 64 + lane * 2;

        #pragma unroll
        for (int kt = 0; kt < 4; kt++) {
            uint4 a[2];
            a[0] = *reinterpret_cast<const uint4*>(aw + kt * 128);
            a[1] = *reinterpret_cast<const uint4*>(aw + (4 + kt) * 128);
            uint2 b[8];
            #pragma unroll
            for (int j = 0; j < 8; j++)
                b[j] = *reinterpret_cast<const uint2*>(bw + (j * 4 + kt) * 64);
            #pragma unroll
            for (int i = 0; i < 2; i++)
                #pragma unroll
                for (int j = 0; j < 8; j++)
                    mma_tf32(acc[i][j][0], acc[i][j][1], acc[i][j][2], acc[i][j][3],
                             a[i].x, a[i].y, a[i].z, a[i].w, b[j].x, b[j].y);
        }
    }

    #pragma unroll
    for (int i = 0; i < 2; i++) {
        #pragma unroll
        for (int h = 0; h < 2; h++) {
            const int m    = bm * 64 + wm * 32 + i * 16 + h * 8 + (lane >> 2);
            const int slot = t2s[m];
            const float sc = (slot >= 0) ? scal[slot] : 0.f;
            const int mt = m >> 4, row = m & 15;
            const int rowoff = (row & 7) * 4, regbit = row >> 3;
            float* ublk = g_u + (size_t)mt * 16 * 128;
            #pragma unroll
            for (int j = 0; j < 8; j++) {
                #pragma unroll
                for (int r = 0; r < 2; r++) {
                    const int nn  = wn * 64 + j * 8 + (lane & 3) * 2 + r;
                    const int kb  = nn >> 3, col = nn & 7;
                    const int off = (rowoff + (col & 3)) * 4 + regbit + 2 * (col >> 2);
                    const float val = ((nn >> 4) == slot)
                                      ? rna(acc[i][j][h * 2 + r] * sc) : 0.f;
                    ublk[kb * 128 + off] = val;
                }
            }
        }
    }
}

// ---------------------------------------------------------------------------
// Pass B: y = x @ W^T (+ LoRA K-ext) + bias.
// CTA 128x128, 128 threads (4 warps, warp 64x64), BK=32, 3 stages, 96KB, occ 2.
// ---------------------------------------------------------------------------
__global__ void __launch_bounds__(128, 2) gemm_main(
    float* __restrict__ C, const float* __restrict__ bias)
{
    constexpr int A_ST = 128 * 32, B_ST = 128 * 32, STW = A_ST + B_ST;
    extern __shared__ float sm[];
    const int tid = threadIdx.x, lane = tid & 31, warp = tid >> 5;
    const int wm = warp >> 1, wn = warp & 1;   // warp tile 64x64
    const int bm = blockIdx.y, bn = blockIdx.x;

    float acc[4][8][4];
    #pragma unroll
    for (int i = 0; i < 4; i++)
        #pragma unroll
        for (int j = 0; j < 8; j++)
            #pragma unroll
            for (int k = 0; k < 4; k++) acc[i][j][k] = 0.f;

    auto load_stage = [&](int f, int buf) {
        float* sA = sm + buf * STW;
        float* sB = sA + A_ST;
        #pragma unroll
        for (int q = tid; q < 128 * 8; q += 128) {
            const int mt = q >> 7, rem = q & 127, kt = rem >> 5, c = rem & 31;
            const float* src = (f < 128)
                ? g_xc + ((size_t)(bm * 8 + mt) * KB_MAIN + f * 4 + kt) * 128 + c * 4
                : g_u  + ((size_t)(bm * 8 + mt) * KB_EXT + (f - 128) * 4 + kt) * 128 + c * 4;
            cpa16(sA + (mt * 4 + kt) * 128 + c * 4, src);
        }
        #pragma unroll
        for (int q = tid; q < 128 * 8; q += 128) {
            const int nt = q >> 6, kt = (q >> 4) & 3, c = q & 15;
            const float* src = (f < 128)
                ? g_wc   + ((size_t)(bn * 16 + nt) * KB_MAIN + f * 4 + kt) * 64 + c * 4
                : g_bcat + ((size_t)(bn * 16 + nt) * KB_EXT + (f - 128) * 4 + kt) * 64 + c * 4;
            cpa16(sB + (nt * 4 + kt) * 64 + c * 4, src);
        }
    };

    load_stage(0, 0); cpcommit();
    load_stage(1, 1); cpcommit();

    for (int ci = 0; ci < 132; ci++) {
        cpwait<1>();
        __syncthreads();
        if (ci + 2 < 132) load_stage(ci + 2, (ci + 2) % 3);
        cpcommit();

        const uint32_t* sA = reinterpret_cast<const uint32_t*>(sm + (ci % 3) * STW);
        const uint32_t* sB = sA + A_ST;
        const uint32_t* aw = sA + (wm * 4) * 4 * 128 + lane * 4;
        const uint32_t* bw = sB + (wn * 8) * 4 * 64 + lane * 2;

        #pragma unroll
        for (int kt = 0; kt < 4; kt++) {
            uint4 a[4];
            #pragma unroll
            for (int i = 0; i < 4; i++)
                a[i] = *reinterpret_cast<const uint4*>(aw + (i * 4 + kt) * 128);
            uint2 b[8];
            #pragma unroll
            for (int j = 0; j < 8; j++)
                b[j] = *reinterpret_cast<const uint2*>(bw + (j * 4 + kt) * 64);
            #pragma unroll
            for (int i = 0; i < 4; i++)
                #pragma unroll
                for (int j = 0; j < 8; j++)
                    mma_tf32(acc[i][j][0], acc[i][j][1], acc[i][j][2], acc[i][j][3],
                             a[i].x, a[i].y, a[i].z, a[i].w, b[j].x, b[j].y);
        }
    }

    const int nb = bn * 128 + wn * 64;
    #pragma unroll
    for (int i = 0; i < 4; i++) {
        #pragma unroll
        for (int h = 0; h < 2; h++) {
            const int m = bm * 128 + wm * 64 + i * 16 + h * 8 + (lane >> 2);
            float* crow = C + (size_t)m * DOUT + nb + (lane & 3) * 2;
            #pragma unroll
            for (int j = 0; j < 8; j++) {
                const float2 bv = *reinterpret_cast<const float2*>(
                    bias + nb + j * 8 + (lane & 3) * 2);
                float2 v;
                v.x = acc[i][j][h * 2 + 0] + bv.x;
                v.y = acc[i][j][h * 2 + 1] + bv.y;
                *reinterpret_cast<float2*>(crow + j * 8) = v;
            }
        }
    }
}

// ---------------------------------------------------------------------------
extern "C" void kernel_launch(void* const* d_in, const int* in_sizes, int n_in,
                              void* d_out, int out_size)
{
    const float* x    = (const float*)d_in[0];
    const int*   t2s  = (const int*)  d_in[1];
    const float* w    = (const float*)d_in[2];
    const float* bias = (const float*)d_in[3];
    const float* lA   = (const float*)d_in[4];
    const float* lB   = (const float*)d_in[5];
    const float* scal = (const float*)d_in[6];
    float*       y    = (float*)d_out;

    constexpr int SMEM0 = 3 * (64 + 128) * 32 * 4;   // 72 KB
    constexpr int SMEM1 = 3 * (128 + 128) * 32 * 4;  // 96 KB

    cudaFuncSetAttribute(gemm_lora, cudaFuncAttributeMaxDynamicSharedMemorySize, SMEM0);
    cudaFuncSetAttribute(gemm_main, cudaFuncAttributeMaxDynamicSharedMemorySize, SMEM1);

    conv_kernel<<<1184, 256>>>(x, w, lA, lB);
    gemm_lora<<<dim3(1, TOK / 64), 128, SMEM0>>>(t2s, scal);
    gemm_main<<<dim3(DOUT / 128, TOK / 128), 128, SMEM1>>>(y, bias);
}

// round 6
// speedup vs baseline: 2.1162x; 1.9972x over previous
#include <cuda_runtime.h>
#include <cuda_fp16.h>
#include <cstdint>

// ---------------------------------------------------------------------------
// LoRARowParallelLinear, mma.sync fp16 m16n8k16 (compute_103-safe).
//   conv:   repack x, W, lora_A into FRAGMENT-MAJOR packed-half2 layouts
//           (rn conversion == tf32-precision mantissa); build Bcat fp16.
//   pass A: u[T,128] = mask*scal*(x @ lora_A^T), written as fp16 A-frag.
//   pass B: y = x @ W^T (K=4096) + u @ Bcat^T (K-ext 128, same accum) + bias.
// A-block (16m x 16k) = 512B: lane l LDS.128 at l*16 -> a0..a3.
// B-block (8n x 16k) = 256B: lane l LDS.64 at l*8 -> b0,b1.
// ---------------------------------------------------------------------------

#define DEVINL static __device__ __forceinline__

namespace {
constexpr int TOK = 8192, DIN = 4096, DOUT = 4096;
constexpr int KB = DIN / 16;   // 256 fp16 k-blocks
}

// scratch (allocation-free __device__ globals), packed half2 words, frag-major
__device__ __align__(128) uint32_t g_xh  [(TOK / 16) * KB * 128];  // 67 MB
__device__ __align__(128) uint32_t g_wh  [(DOUT / 8) * KB * 64];   // 33.5 MB
__device__ __align__(128) uint32_t g_lah [16 * KB * 64];           // 1 MB
__device__ __align__(128) uint32_t g_bcat[(DOUT / 8) * 8 * 64];    // 1 MB
__device__ __align__(128) uint32_t g_uh  [(TOK / 16) * 8 * 128];   // 2 MB

DEVINL uint32_t h2pack(float lo, float hi) {
    __half2 h = __float22half2_rn(make_float2(lo, hi));
    return *reinterpret_cast<uint32_t*>(&h);
}

DEVINL void mma_f16(float& d0, float& d1, float& d2, float& d3,
                    uint32_t a0, uint32_t a1, uint32_t a2, uint32_t a3,
                    uint32_t b0, uint32_t b1)
{
    asm volatile(
        "mma.sync.aligned.m16n8k16.row.col.f32.f16.f16.f32 "
        "{%0,%1,%2,%3},{%4,%5,%6,%7},{%8,%9},{%0,%1,%2,%3};"
        : "+f"(d0), "+f"(d1), "+f"(d2), "+f"(d3)
        : "r"(a0), "r"(a1), "r"(a2), "r"(a3), "r"(b0), "r"(b1));
}

DEVINL void cpa16(const uint32_t* smem_dst, const void* gsrc) {
    uint32_t s = (uint32_t)__cvta_generic_to_shared(smem_dst);
    asm volatile("cp.async.cg.shared.global [%0], [%1], 16;" :: "r"(s), "l"(gsrc));
}
DEVINL void cpcommit() { asm volatile("cp.async.commit_group;"); }
template <int N> DEVINL void cpwait() { asm volatile("cp.async.wait_group %0;" :: "n"(N)); }

// ---------------------------------------------------------------------------
// Conversion: fp32 -> packed fp16 frag-major, staged through smem.
// ---------------------------------------------------------------------------
__global__ void __launch_bounds__(256) conv_kernel(
    const float* __restrict__ x, const float* __restrict__ w,
    const float* __restrict__ la, const float* __restrict__ lb)
{
    __shared__ float st[8][16 * 36];
    const int tid  = threadIdx.x;
    const int lane = tid & 31, warp = tid >> 5;
    const int gwarp = blockIdx.x * 8 + warp;
    const int nwarp = gridDim.x * 8;
    float* s = st[warp];
    const int g  = lane >> 2;
    const int k0 = (lane & 3) * 2;

    // x -> g_xh (A-frag). Superblock = 16 rows x 32 cols (2 k-blocks).
    {
        const int r = lane >> 1, coff = (lane & 1) * 16;
        for (int sb = gwarp; sb < 512 * 128; sb += nwarp) {
            const int mt = sb >> 7, kt2 = sb & 127;
            const float* base = x + (size_t)(mt * 16) * DIN + kt2 * 32;
            #pragma unroll
            for (int q = 0; q < 4; q++)
                *reinterpret_cast<float4*>(s + r * 36 + coff + q * 4) =
                    *reinterpret_cast<const float4*>(base + (size_t)r * DIN + coff + q * 4);
            __syncwarp();
            #pragma unroll
            for (int kb = 0; kb < 2; kb++) {
                const int K = kb * 16;
                uint4 v;
                v.x = h2pack(s[g * 36 + K + k0],           s[g * 36 + K + k0 + 1]);
                v.y = h2pack(s[(g + 8) * 36 + K + k0],     s[(g + 8) * 36 + K + k0 + 1]);
                v.z = h2pack(s[g * 36 + K + k0 + 8],       s[g * 36 + K + k0 + 9]);
                v.w = h2pack(s[(g + 8) * 36 + K + k0 + 8], s[(g + 8) * 36 + K + k0 + 9]);
                *reinterpret_cast<uint4*>(
                    g_xh + ((size_t)mt * KB + kt2 * 2 + kb) * 128 + lane * 4) = v;
            }
            __syncwarp();
        }
    }

    // w -> g_wh (B-frag). Superblock = 8 rows x 32 cols (2 k-blocks).
    {
        const int r = lane >> 2, coff = (lane & 3) * 8;
        for (int sb = gwarp; sb < 512 * 128; sb += nwarp) {
            const int nt = sb >> 7, kt2 = sb & 127;
            const float* base = w + (size_t)(nt * 8) * DIN + kt2 * 32;
            #pragma unroll
            for (int q = 0; q < 2; q++)
                *reinterpret_cast<float4*>(s + r * 36 + coff + q * 4) =
                    *reinterpret_cast<const float4*>(base + (size_t)r * DIN + coff + q * 4);
            __syncwarp();
            #pragma unroll
            for (int kb = 0; kb < 2; kb++) {
                const int K = kb * 16;
                uint2 v;
                v.x = h2pack(s[g * 36 + K + k0],     s[g * 36 + K + k0 + 1]);
                v.y = h2pack(s[g * 36 + K + k0 + 8], s[g * 36 + K + k0 + 9]);
                *reinterpret_cast<uint2*>(
                    g_wh + ((size_t)nt * KB + kt2 * 2 + kb) * 64 + lane * 2) = v;
            }
            __syncwarp();
        }
    }

    // lora_A -> g_lah (B-frag, 16 n-tiles)
    {
        const int r = lane >> 2, coff = (lane & 3) * 8;
        for (int sb = gwarp; sb < 16 * 128; sb += nwarp) {
            const int nt = sb >> 7, kt2 = sb & 127;
            const float* base = la + (size_t)(nt * 8) * DIN + kt2 * 32;
            #pragma unroll
            for (int q = 0; q < 2; q++)
                *reinterpret_cast<float4*>(s + r * 36 + coff + q * 4) =
                    *reinterpret_cast<const float4*>(base + (size_t)r * DIN + coff + q * 4);
            __syncwarp();
            #pragma unroll
            for (int kb = 0; kb < 2; kb++) {
                const int K = kb * 16;
                uint2 v;
                v.x = h2pack(s[g * 36 + K + k0],     s[g * 36 + K + k0 + 1]);
                v.y = h2pack(s[g * 36 + K + k0 + 8], s[g * 36 + K + k0 + 9]);
                *reinterpret_cast<uint2*>(
                    g_lah + ((size_t)nt * KB + kt2 * 2 + kb) * 64 + lane * 2) = v;
            }
            __syncwarp();
        }
    }

    // lora_B [8][DOUT][16] -> g_bcat (B-frag [DOUT/8][8][64w]): Bcat[n][s*16+r]=lB[s][n][r]
    const int nth = gridDim.x * blockDim.x;
    const int gt  = blockIdx.x * 256 + tid;
    for (int i = gt; i < DOUT * 64; i += nth) {
        const int n = i >> 6, p = i & 63;
        const int kc = p * 2;
        const int sl = kc >> 4, r = kc & 15;
        const float f0 = lb[(size_t)sl * DOUT * 16 + n * 16 + r];
        const float f1 = lb[(size_t)sl * DOUT * 16 + n * 16 + r + 1];
        const int nt = n >> 3, gg = n & 7;
        const int kbb  = kc >> 4;
        const int lpos = gg * 4 + ((kc & 7) >> 1);
        const int word = lpos * 2 + ((kc >> 3) & 1);
        g_bcat[((size_t)nt * 8 + kbb) * 64 + word] = h2pack(f0, f1);
    }
}

// ---------------------------------------------------------------------------
// Pass A: u = mask*scal*(x @ lora_A^T) -> g_uh (fp16 A-frag).
// CTA 64x128, 128 thr (4 warps, warp 32x64), BK=32, 4 stages, 48KB.
// ---------------------------------------------------------------------------
__global__ void __launch_bounds__(128, 3) gemm_lora(
    const int* __restrict__ t2s, const float* __restrict__ scal)
{
    constexpr int A_ST = 1024, B_ST = 2048, STW = A_ST + B_ST;  // words
    extern __shared__ uint32_t sm[];
    const int tid = threadIdx.x, lane = tid & 31, warp = tid >> 5;
    const int wm = warp >> 1, wn = warp & 1;
    const int bm = blockIdx.y;

    float acc[2][8][4];
    #pragma unroll
    for (int i = 0; i < 2; i++)
        #pragma unroll
        for (int j = 0; j < 8; j++)
            #pragma unroll
            for (int k = 0; k < 4; k++) acc[i][j][k] = 0.f;

    auto load_stage = [&](int f, int buf) {
        uint32_t* sA = sm + buf * STW;
        uint32_t* sB = sA + A_ST;
        #pragma unroll
        for (int q = tid; q < 256; q += 128) {
            const int mt = q >> 6, kb = (q >> 5) & 1, c = q & 31;
            cpa16(sA + (mt * 2 + kb) * 128 + c * 4,
                  g_xh + ((size_t)(bm * 4 + mt) * KB + f * 2 + kb) * 128 + c * 4);
        }
        #pragma unroll
        for (int q = tid; q < 512; q += 128) {
            const int nt = q >> 5, kb = (q >> 4) & 1, c = q & 15;
            cpa16(sB + (nt * 2 + kb) * 64 + c * 4,
                  g_lah + ((size_t)nt * KB + f * 2 + kb) * 64 + c * 4);
        }
    };

    load_stage(0, 0); cpcommit();
    load_stage(1, 1); cpcommit();
    load_stage(2, 2); cpcommit();

    for (int ci = 0; ci < 128; ci++) {
        cpwait<2>();
        __syncthreads();
        if (ci + 3 < 128) load_stage(ci + 3, (ci + 3) & 3);
        cpcommit();

        const uint32_t* sA = sm + (ci & 3) * STW;
        const uint32_t* sB = sA + A_ST;
        const uint32_t* aw = sA + (wm * 2) * 2 * 128 + lane * 4;
        const uint32_t* bw = sB + (wn * 8) * 2 * 64 + lane * 2;

        #pragma unroll
        for (int kb = 0; kb < 2; kb++) {
            uint4 a[2];
            a[0] = *reinterpret_cast<const uint4*>(aw + kb * 128);
            a[1] = *reinterpret_cast<const uint4*>(aw + (2 + kb) * 128);
            uint2 b[8];
            #pragma unroll
            for (int j = 0; j < 8; j++)
                b[j] = *reinterpret_cast<const uint2*>(bw + (j * 2 + kb) * 64);
            #pragma unroll
            for (int i = 0; i < 2; i++)
                #pragma unroll
                for (int j = 0; j < 8; j++)
                    mma_f16(acc[i][j][0], acc[i][j][1], acc[i][j][2], acc[i][j][3],
                            a[i].x, a[i].y, a[i].z, a[i].w, b[j].x, b[j].y);
        }
    }

    // epilogue: mask*scale -> fp16 A-frag blocks of g_uh.
    // c-frag (row g: c0,c1 / row g+8: c2,c3) maps directly onto A-frag regs.
    #pragma unroll
    for (int i = 0; i < 2; i++) {
        const int mrow0 = bm * 64 + wm * 32 + i * 16 + (lane >> 2);
        const int slot0 = t2s[mrow0];
        const int slot1 = t2s[mrow0 + 8];
        const float sc0 = scal[slot0];
        const float sc1 = scal[slot1];
        const int mt = bm * 4 + wm * 2 + i;
        #pragma unroll
        for (int j = 0; j < 8; j += 2) {
            const int kbg = wn * 4 + (j >> 1);
            const int n0 = wn * 64 + j * 8 + (lane & 3) * 2;
            const int n1 = n0 + 8;
            const float m00 = ((n0 >> 4) == slot0) ? sc0 : 0.f;
            const float m01 = ((n0 >> 4) == slot1) ? sc1 : 0.f;
            const float m10 = ((n1 >> 4) == slot0) ? sc0 : 0.f;
            const float m11 = ((n1 >> 4) == slot1) ? sc1 : 0.f;
            uint4 v;
            v.x = h2pack(acc[i][j][0] * m00,     acc[i][j][1] * m00);
            v.y = h2pack(acc[i][j][2] * m01,     acc[i][j][3] * m01);
            v.z = h2pack(acc[i][j + 1][0] * m10, acc[i][j + 1][1] * m10);
            v.w = h2pack(acc[i][j + 1][2] * m11, acc[i][j + 1][3] * m11);
            *reinterpret_cast<uint4*>(g_uh + ((size_t)mt * 8 + kbg) * 128 + lane * 4) = v;
        }
    }
}

// ---------------------------------------------------------------------------
// Pass B: y = x @ W^T (+ LoRA K-ext) + bias.
// CTA 128x128, 128 thr (4 warps, warp 64x64), BK=32, 4 stages, 64KB, occ 2.
// ---------------------------------------------------------------------------
__global__ void __launch_bounds__(128, 2) gemm_main(
    float* __restrict__ C, const float* __restrict__ bias)
{
    constexpr int A_ST = 2048, B_ST = 2048, STW = A_ST + B_ST;  // words
    extern __shared__ uint32_t sm[];
    const int tid = threadIdx.x, lane = tid & 31, warp = tid >> 5;
    const int wm = warp >> 1, wn = warp & 1;
    const int bm = blockIdx.y, bn = blockIdx.x;

    float acc[4][8][4];
    #pragma unroll
    for (int i = 0; i < 4; i++)
        #pragma unroll
        for (int j = 0; j < 8; j++)
            #pragma unroll
            for (int k = 0; k < 4; k++) acc[i][j][k] = 0.f;

    auto load_stage = [&](int f, int buf) {
        uint32_t* sA = sm + buf * STW;
        uint32_t* sB = sA + A_ST;
        #pragma unroll
        for (int q = tid; q < 512; q += 128) {
            const int mt = q >> 6, kb = (q >> 5) & 1, c = q & 31;
            const uint32_t* src = (f < 128)
                ? g_xh + ((size_t)(bm * 8 + mt) * KB + f * 2 + kb) * 128 + c * 4
                : g_uh + ((size_t)(bm * 8 + mt) * 8 + (f - 128) * 2 + kb) * 128 + c * 4;
            cpa16(sA + (mt * 2 + kb) * 128 + c * 4, src);
        }
        #pragma unroll
        for (int q = tid; q < 512; q += 128) {
            const int nt = q >> 5, kb = (q >> 4) & 1, c = q & 15;
            const uint32_t* src = (f < 128)
                ? g_wh   + ((size_t)(bn * 16 + nt) * KB + f * 2 + kb) * 64 + c * 4
                : g_bcat + ((size_t)(bn * 16 + nt) * 8 + (f - 128) * 2 + kb) * 64 + c * 4;
            cpa16(sB + (nt * 2 + kb) * 64 + c * 4, src);
        }
    };

    load_stage(0, 0); cpcommit();
    load_stage(1, 1); cpcommit();
    load_stage(2, 2); cpcommit();

    for (int ci = 0; ci < 132; ci++) {
        cpwait<2>();
        __syncthreads();
        if (ci + 3 < 132) load_stage(ci + 3, (ci + 3) & 3);
        cpcommit();

        const uint32_t* sA = sm + (ci & 3) * STW;
        const uint32_t* sB = sA + A_ST;
        const uint32_t* aw = sA + (wm * 4) * 2 * 128 + lane * 4;
        const uint32_t* bw = sB + (wn * 8) * 2 * 64 + lane * 2;

        #pragma unroll
        for (int kb = 0; kb < 2; kb++) {
            uint4 a[4];
            #pragma unroll
            for (int i = 0; i < 4; i++)
                a[i] = *reinterpret_cast<const uint4*>(aw + (i * 2 + kb) * 128);
            uint2 b[8];
            #pragma unroll
            for (int j = 0; j < 8; j++)
                b[j] = *reinterpret_cast<const uint2*>(bw + (j * 2 + kb) * 64);
            #pragma unroll
            for (int i = 0; i < 4; i++)
                #pragma unroll
                for (int j = 0; j < 8; j++)
                    mma_f16(acc[i][j][0], acc[i][j][1], acc[i][j][2], acc[i][j][3],
                            a[i].x, a[i].y, a[i].z, a[i].w, b[j].x, b[j].y);
        }
    }

    // epilogue: + bias -> y
    const int nb = bn * 128 + wn * 64;
    #pragma unroll
    for (int i = 0; i < 4; i++) {
        #pragma unroll
        for (int h = 0; h < 2; h++) {
            const int m = bm * 128 + wm * 64 + i * 16 + h * 8 + (lane >> 2);
            float* crow = C + (size_t)m * DOUT + nb + (lane & 3) * 2;
            #pragma unroll
            for (int j = 0; j < 8; j++) {
                const float2 bv = *reinterpret_cast<const float2*>(
                    bias + nb + j * 8 + (lane & 3) * 2);
                float2 v;
                v.x = acc[i][j][h * 2 + 0] + bv.x;
                v.y = acc[i][j][h * 2 + 1] + bv.y;
                *reinterpret_cast<float2*>(crow + j * 8) = v;
            }
        }
    }
}

// ---------------------------------------------------------------------------
extern "C" void kernel_launch(void* const* d_in, const int* in_sizes, int n_in,
                              void* d_out, int out_size)
{
    const float* x    = (const float*)d_in[0];
    const int*   t2s  = (const int*)  d_in[1];
    const float* w    = (const float*)d_in[2];
    const float* bias = (const float*)d_in[3];
    const float* lA   = (const float*)d_in[4];
    const float* lB   = (const float*)d_in[5];
    const float* scal = (const float*)d_in[6];
    float*       y    = (float*)d_out;

    constexpr int SMEM0 = 4 * (1024 + 2048) * 4;  // 48 KB
    constexpr int SMEM1 = 4 * (2048 + 2048) * 4;  // 64 KB

    cudaFuncSetAttribute(gemm_lora, cudaFuncAttributeMaxDynamicSharedMemorySize, SMEM0);
    cudaFuncSetAttribute(gemm_main, cudaFuncAttributeMaxDynamicSharedMemorySize, SMEM1);

    conv_kernel<<<1184, 256>>>(x, w, lA, lB);
    gemm_lora<<<dim3(1, TOK / 64), 128, SMEM0>>>(t2s, scal);
    gemm_main<<<dim3(DOUT / 128, TOK / 128), 128, SMEM1>>>(y, bias);
}